// round 14
// baseline (speedup 1.0000x reference)
#include <cuda_runtime.h>
#include <cuda_bf16.h>
#include <cstdint>

#define MROWS 16384
#define NCODES 16384
#define DDIM 256
#define OUT_ELEMS (16 * 256 * 32 * 32)   // 4194304

#define BM 128                 // rows per CTA
#define BN 128                 // codebook rows per chunk
#define NCHUNK (NCODES / BN)   // 128
#define CAP 128
#define MARGIN_P 4e-4f
#define QSCALE 51200.0f        // int8 quant scale; ulp = 1.953e-5
#define QSLACK 2.5e-5f         // > half-ulp + fp fuzz
#define GTHREADS 512

#define ASTRIDE 264            // bf16 elems per smem row (256 + 8 pad)
#define ROWB (ASTRIDE * 2)     // 528 bytes; 528 % 128 = 16 -> conflict-free ldmatrix

// ---- device scratch ----
__device__ float          g_Zt[MROWS * DDIM];     // fp32 transposed z
__device__ __nv_bfloat16  g_Ztb[MROWS * DDIM];    // bf16 transposed z
__device__ __nv_bfloat16  g_CBb[NCODES * DDIM];   // bf16 codebook
__device__ signed char    g_P8[(size_t)MROWS * NCODES];  // 256 MB quantized scores
__device__ float          g_rowmaxf[MROWS];       // final per-row max p (fp32)
__device__ float          g_A[MROWS];             // |z_row|^2
__device__ int            g_cnt[MROWS];           // candidate counts
__device__ int            g_list[MROWS * CAP];    // candidate codebook indices
__device__ int            g_idx[MROWS];           // final argmin index
__device__ float          g_partial[MROWS];       // per-row sum (e-z)^2

// ======================= portable PTX helpers (sm_80+) =======================
__device__ __forceinline__ uint32_t smem_u32(const void* p) {
    uint32_t a;
    asm("{ .reg .u64 t; cvta.to.shared.u64 t, %1; cvt.u32.u64 %0, t; }" : "=r"(a) : "l"(p));
    return a;
}
__device__ __forceinline__ void ldmat4(uint32_t* r, uint32_t addr) {
    asm volatile("ldmatrix.sync.aligned.m8n8.x4.shared.b16 {%0,%1,%2,%3}, [%4];"
                 : "=r"(r[0]), "=r"(r[1]), "=r"(r[2]), "=r"(r[3]) : "r"(addr));
}
__device__ __forceinline__ void mma16816(float* d, const uint32_t* a,
                                         uint32_t b0, uint32_t b1) {
    asm volatile(
        "mma.sync.aligned.m16n8k16.row.col.f32.bf16.bf16.f32 "
        "{%0,%1,%2,%3}, {%4,%5,%6,%7}, {%8,%9}, {%0,%1,%2,%3};"
        : "+f"(d[0]), "+f"(d[1]), "+f"(d[2]), "+f"(d[3])
        : "r"(a[0]), "r"(a[1]), "r"(a[2]), "r"(a[3]), "r"(b0), "r"(b1));
}
__device__ __forceinline__ void cp_async16(uint32_t dst, const void* src) {
    asm volatile("cp.async.cg.shared.global [%0], [%1], 16;" :: "r"(dst), "l"(src));
}
#define CP_COMMIT() asm volatile("cp.async.commit_group;" ::: "memory")
#define CP_WAIT0()  asm volatile("cp.async.wait_group 0;" ::: "memory")

__device__ __forceinline__ int q8(float p) {
    return __float2int_rn(fminf(fmaxf(p * QSCALE, -127.0f), 127.0f));
}

// ======================= transpose + bf16 cast of z =======================
__global__ void k_transpose(const float* __restrict__ z) {
    __shared__ float tile[32][33];
    const int b  = blockIdx.z;
    const int c0 = blockIdx.y * 32;
    const int h0 = blockIdx.x * 32;
    const int tx = threadIdx.x, ty = threadIdx.y;
#pragma unroll
    for (int i = 0; i < 32; i += 8)
        tile[ty + i][tx] = z[(b * 256 + c0 + ty + i) * 1024 + h0 + tx];
    __syncthreads();
#pragma unroll
    for (int i = 0; i < 32; i += 8) {
        const float v = tile[tx][ty + i];
        const int   o = (b * 1024 + h0 + ty + i) * 256 + c0 + tx;
        g_Zt[o]  = v;
        g_Ztb[o] = __float2bfloat16(v);
    }
}

// ======================= codebook -> bf16 =======================
__global__ void k_castcb(const float* __restrict__ cb) {
    const int i = blockIdx.x * 256 + threadIdx.x;     // over float2 elems
    float2 v = reinterpret_cast<const float2*>(cb)[i];
    reinterpret_cast<__nv_bfloat162*>(g_CBb)[i] = __float22bfloat162_rn(v);
}

// ======================= per-row |z|^2  (+ zero cand counts) ==============
__global__ void k_rownorm() {
    const int row = blockIdx.x;
    const int tid = threadIdx.x;
    float v = g_Zt[row * DDIM + tid];
    float s = v * v;
#pragma unroll
    for (int o = 16; o > 0; o >>= 1) s += __shfl_down_sync(0xffffffffu, s, o);
    __shared__ float red[8];
    if ((tid & 31) == 0) red[tid >> 5] = s;
    __syncthreads();
    if (tid == 0) {
        float t = red[0];
#pragma unroll
        for (int w = 1; w < 8; w++) t += red[w];
        g_A[row] = t;
        g_cnt[row] = 0;
    }
}

// ======================= single-pass bf16 mma.sync GEMM + int8 P store =====
// Grid: 128 CTAs x 512 threads (16 warps: 4 m-blocks x 4 n-blocks, 32x32 tile).
// Per chunk: MMA -> quantize scores to int8, stage into the just-consumed B
// smem buffer (dead after the kk loop; prefetch targets the other buffer),
// dump 16 KB coalesced to g_P8, fold fp32 per-lane rowmax.
__global__ void __launch_bounds__(GTHREADS, 1) k_gemm_store() {
    extern __shared__ char dsm[];
    char* smA  = dsm;                       // 128*528 = 67584 B
    char* smB0 = dsm + 67584;
    char* smB1 = dsm + 2 * 67584;

    __shared__ float s_cmax[BM][4];

    const int tid = threadIdx.x;
    const int wid = tid >> 5;
    const int lid = tid & 31;
    const int m0  = blockIdx.x * BM;
    const int wm  = wid & 3;                // m-block (32 rows)
    const int wn  = wid >> 2;               // n-block (32 cols)

    // ---- stage A (rows m0..m0+127), padded rows ----
    for (int i = tid; i < 4096; i += GTHREADS) {
        const int r = i >> 5, c = i & 31;
        uint4 v = *reinterpret_cast<const uint4*>(
            g_Ztb + (size_t)(m0 + r) * DDIM + c * 8);
        *reinterpret_cast<uint4*>(smA + r * ROWB + c * 16) = v;
    }
    // ---- stage B chunk 0 via cp.async ----
    {
        const uint32_t b0 = smem_u32(smB0);
        for (int i = tid; i < 4096; i += GTHREADS) {
            const int r = i >> 5, c = i & 31;
            cp_async16(b0 + r * ROWB + c * 16, g_CBb + (size_t)r * DDIM + c * 8);
        }
        CP_COMMIT();
    }
    CP_WAIT0();
    __syncthreads();

    // ldmatrix lane bases. x4: lanes 0-15 rows (lid&15) @+0, 16-31 @+16B.
    const uint32_t aBase =
        smem_u32(smA) + (wm * 32 + (lid & 15)) * ROWB + (lid >> 4) * 16;
    const uint32_t bOff = (wn * 32 + (lid & 15)) * ROWB + (lid >> 4) * 16;
    const uint32_t bBase0 = smem_u32(smB0) + bOff;
    const uint32_t bBase1 = smem_u32(smB1) + bOff;

    // per-lane running maxes: [mi] x {low rows, high rows}
    float rmlow[2]  = {-3.4e38f, -3.4e38f};
    float rmhigh[2] = {-3.4e38f, -3.4e38f};

    const int rl0  = wm * 32 + (lid >> 2);      // mi=0 low row (local)
    const int colq = wn * 32 + 2 * (lid & 3);   // lane col base within chunk

    for (int c = 0; c < NCHUNK; c++) {
        const int buf = c & 1;
        // prefetch B(c+1) into the other buffer (overlaps MMA on chunk c)
        if (c + 1 < NCHUNK) {
            const uint32_t bd = smem_u32(buf ? smB0 : smB1);
            const size_t nbase = (size_t)(c + 1) * BN;
            for (int i = tid; i < 4096; i += GTHREADS) {
                const int r = i >> 5, cc = i & 31;
                cp_async16(bd + r * ROWB + cc * 16,
                           g_CBb + (nbase + r) * DDIM + cc * 8);
            }
        }
        CP_COMMIT();

        const uint32_t bB = buf ? bBase1 : bBase0;
        float acc[2][4][4];
#pragma unroll
        for (int mi = 0; mi < 2; mi++)
#pragma unroll
            for (int nj = 0; nj < 4; nj++)
#pragma unroll
                for (int t = 0; t < 4; t++) acc[mi][nj][t] = 0.0f;

        // frag double-buffer: [buf][0]=A rows 0-15, [1]=A rows 16-31,
        //                     [2]=B cols 0-15, [3]=B cols 16-31
        uint32_t fr[2][4][4];
        ldmat4(fr[0][0], aBase);
        ldmat4(fr[0][1], aBase + 16 * ROWB);
        ldmat4(fr[0][2], bB);
        ldmat4(fr[0][3], bB + 16 * ROWB);
#pragma unroll
        for (int kk = 0; kk < 16; kk++) {
            const int cu = kk & 1, nx = cu ^ 1;
            if (kk < 15) {
                ldmat4(fr[nx][0], aBase + (kk + 1) * 32);
                ldmat4(fr[nx][1], aBase + 16 * ROWB + (kk + 1) * 32);
                ldmat4(fr[nx][2], bB + (kk + 1) * 32);
                ldmat4(fr[nx][3], bB + 16 * ROWB + (kk + 1) * 32);
            }
            mma16816(acc[0][0], fr[cu][0], fr[cu][2][0], fr[cu][2][2]);
            mma16816(acc[0][1], fr[cu][0], fr[cu][2][1], fr[cu][2][3]);
            mma16816(acc[1][0], fr[cu][1], fr[cu][2][0], fr[cu][2][2]);
            mma16816(acc[1][1], fr[cu][1], fr[cu][2][1], fr[cu][2][3]);
            mma16816(acc[0][2], fr[cu][0], fr[cu][3][0], fr[cu][3][2]);
            mma16816(acc[0][3], fr[cu][0], fr[cu][3][1], fr[cu][3][3]);
            mma16816(acc[1][2], fr[cu][1], fr[cu][3][0], fr[cu][3][2]);
            mma16816(acc[1][3], fr[cu][1], fr[cu][3][1], fr[cu][3][3]);
        }

        // ---- epilogue: quantize -> stage int8 in the consumed B buffer ----
        char* stage = buf ? smB1 : smB0;    // chunk c's B data is dead now
#pragma unroll
        for (int mi = 0; mi < 2; mi++) {
            const int rL = rl0 + mi * 16;
#pragma unroll
            for (int nj = 0; nj < 4; nj++) {
                const float a0 = acc[mi][nj][0], a1 = acc[mi][nj][1];
                const float a2 = acc[mi][nj][2], a3 = acc[mi][nj][3];
                rmlow[mi]  = fmaxf(rmlow[mi],  fmaxf(a0, a1));
                rmhigh[mi] = fmaxf(rmhigh[mi], fmaxf(a2, a3));
                const int off = colq + nj * 8;
                *reinterpret_cast<uint16_t*>(stage + rL * 128 + off) =
                    (uint16_t)((q8(a0) & 0xFF) | ((q8(a1) & 0xFF) << 8));
                *reinterpret_cast<uint16_t*>(stage + (rL + 8) * 128 + off) =
                    (uint16_t)((q8(a2) & 0xFF) | ((q8(a3) & 0xFF) << 8));
            }
        }
        __syncthreads();
        // ---- dump staging -> g_P8 (coalesced 16B stores) ----
        for (int i = tid; i < 1024; i += GTHREADS) {
            uint4 v = *reinterpret_cast<const uint4*>(stage + i * 16);
            const size_t gaddr =
                (size_t)(m0 + (i >> 3)) * NCODES + (size_t)c * BN + (i & 7) * 16;
            *reinterpret_cast<uint4*>(g_P8 + gaddr) = v;
        }
        CP_WAIT0();
        __syncthreads();
    }

    // ---- final rowmax reduce -> g_rowmaxf ----
#pragma unroll
    for (int mi = 0; mi < 2; mi++) {
        float ml = rmlow[mi], mh = rmhigh[mi];
        ml = fmaxf(ml, __shfl_xor_sync(0xffffffffu, ml, 1));
        ml = fmaxf(ml, __shfl_xor_sync(0xffffffffu, ml, 2));
        mh = fmaxf(mh, __shfl_xor_sync(0xffffffffu, mh, 1));
        mh = fmaxf(mh, __shfl_xor_sync(0xffffffffu, mh, 2));
        if ((lid & 3) == 0) {
            const int rl = wm * 32 + mi * 16 + (lid >> 2);
            s_cmax[rl][wn]     = ml;
            s_cmax[rl + 8][wn] = mh;
        }
    }
    __syncthreads();
    if (tid < BM)
        g_rowmaxf[m0 + tid] = fmaxf(fmaxf(s_cmax[tid][0], s_cmax[tid][1]),
                                    fmaxf(s_cmax[tid][2], s_cmax[tid][3]));
}

// ======================= candidate filter over int8 P =======================
// One warp per row (8 warps/block). SIMD byte-compare vs quantized threshold.
// qthr clamped to <=127 so saturated scores (incl. a clamped winner) always pass.
__global__ void __launch_bounds__(256) k_filter() {
    const int wid = threadIdx.x >> 5;
    const int lid = threadIdx.x & 31;
    const int row = blockIdx.x * 8 + wid;
    const float thr = g_rowmaxf[row] - (MARGIN_P + QSLACK);
    int qthr = (int)ceilf(thr * QSCALE);
    if (qthr > 127)  qthr = 127;
    if (qthr < -128) qthr = -128;
    const uint32_t qpat = (uint32_t)(qthr & 0xFF) * 0x01010101u;

    const uint4* prow =
        reinterpret_cast<const uint4*>(g_P8 + (size_t)row * NCODES);
    for (int i = lid; i < 1024; i += 32) {       // 1024 x 16B per row
        const uint4 v = __ldg(prow + i);
        uint32_t w[4] = {v.x, v.y, v.z, v.w};
#pragma unroll
        for (int j = 0; j < 4; j++) {
            uint32_t m = __vcmpges4(w[j], qpat);
            while (m) {                           // rare: ~13 hits / 16384
                const int b = (__ffs(m) - 1) >> 3;
                const int code = i * 16 + j * 4 + b;
                int s = atomicAdd(&g_cnt[row], 1);
                if (s < CAP) g_list[row * CAP + s] = code;
                m &= ~(0xFFu << (b * 8));
            }
        }
    }
}

// ======================= exact rescore + loss partial + idx ================
// One block (256 thr) per row. Rescore replicates R1 bit-exact arithmetic:
// acc = fmaf ascending k;  d = __fadd_rn(A, -2.0f*acc);  min d, tie -> min idx.
__global__ void k_rescore(const float* __restrict__ cb, float* __restrict__ dout,
                          int idx_off) {
    const int row = blockIdx.x;
    const int tid = threadIdx.x;
    __shared__ float zrow[DDIM];
    __shared__ float sd[256];
    __shared__ int   si[256];
    __shared__ int   s_bi;
    __shared__ float red[8];

    zrow[tid] = g_Zt[(size_t)row * DDIM + tid];
    const int cnt = g_cnt[row];
    const float Arow = g_A[row];
    __syncthreads();

    if (cnt <= CAP) {
        float d = __int_as_float(0x7f800000);
        int   bi = 0x7fffffff;
        if (tid < cnt) {
            bi = g_list[row * CAP + tid];
            const float* e = cb + (size_t)bi * DDIM;
            float acc = 0.0f;
#pragma unroll 8
            for (int k = 0; k < DDIM; k++) acc = fmaf(zrow[k], __ldg(e + k), acc);
            d = __fadd_rn(Arow, -2.0f * acc);
        }
        sd[tid] = d; si[tid] = bi;
        __syncthreads();
        for (int o = 128; o > 0; o >>= 1) {
            if (tid < o) {
                float od = sd[tid + o]; int oi = si[tid + o];
                if (od < sd[tid] || (od == sd[tid] && oi < si[tid])) {
                    sd[tid] = od; si[tid] = oi;
                }
            }
            __syncthreads();
        }
        if (tid == 0) s_bi = si[0];
    } else {
        // fallback: exact full scan (expected ~never with full-max threshold)
        float bd = __int_as_float(0x7f800000);
        int   bi = 0x7fffffff;
        for (int n = tid; n < NCODES; n += 256) {
            float acc = 0.0f;
            const float* e = cb + (size_t)n * DDIM;
#pragma unroll 8
            for (int k = 0; k < DDIM; k++) acc = fmaf(zrow[k], e[k], acc);
            float d = __fadd_rn(Arow, -2.0f * acc);
            if (d < bd || (d == bd && n < bi)) { bd = d; bi = n; }
        }
        sd[tid] = bd; si[tid] = bi;
        __syncthreads();
        for (int o = 128; o > 0; o >>= 1) {
            if (tid < o) {
                float od = sd[tid + o]; int oi = si[tid + o];
                if (od < sd[tid] || (od == sd[tid] && oi < si[tid])) {
                    sd[tid] = od; si[tid] = oi;
                }
            }
            __syncthreads();
        }
        if (tid == 0) s_bi = si[0];
    }
    __syncthreads();
    const int bi = s_bi;

    // ---- fused loss partial (bit-exact replica of old k_partial) ----
    const float e  = cb[(size_t)bi * DDIM + tid];
    const float zt = zrow[tid];
    const float t  = __fsub_rn(e, zt);
    float d2 = t * t;
#pragma unroll
    for (int o = 16; o > 0; o >>= 1) d2 += __shfl_down_sync(0xffffffffu, d2, o);
    if ((tid & 31) == 0) red[tid >> 5] = d2;
    __syncthreads();
    if (tid == 0) {
        float tot = red[0];
#pragma unroll
        for (int w = 1; w < 8; w++) tot += red[w];
        g_partial[row] = tot;
        g_idx[row] = bi;
        if (idx_off >= 0) dout[idx_off + row] = (float)bi;
    }
}

// ======================= final loss =======================
__global__ void k_loss(float* __restrict__ dout, int loss_off) {
    const int tid = threadIdx.x;
    float s = 0.0f;
    for (int i = tid; i < MROWS; i += 256) s += g_partial[i];
    __shared__ float red[256];
    red[tid] = s;
    __syncthreads();
    for (int o = 128; o > 0; o >>= 1) {
        if (tid < o) red[tid] += red[tid + o];
        __syncthreads();
    }
    if (tid == 0 && loss_off >= 0)
        dout[loss_off] = 1.25f * red[0] / (float)OUT_ELEMS;
}

// ======================= straight-through output =======================
__global__ void k_output(const float* __restrict__ z, const float* __restrict__ cb,
                         float* __restrict__ dout) {
    const int hw = blockIdx.x * 256 + threadIdx.x;
    const int c  = blockIdx.y;
    const int b  = blockIdx.z;
    const int row = (b << 10) + hw;
    const int n   = g_idx[row];
    const int off = (b * 256 + c) * 1024 + hw;
    const float zv = z[off];
    const float e  = cb[(size_t)n * DDIM + c];
    dout[off] = __fadd_rn(zv, __fsub_rn(e, zv));
}

extern "C" void kernel_launch(void* const* d_in, const int* in_sizes, int n_in,
                              void* d_out, int out_size) {
    const float* z  = (const float*)d_in[0];
    const float* cb = (const float*)d_in[1];
    float* dout = (float*)d_out;

    int loss_off = -1, idx_off = -1;
    if (out_size >= OUT_ELEMS + 1 + MROWS) { loss_off = OUT_ELEMS; idx_off = OUT_ELEMS + 1; }
    else if (out_size >= OUT_ELEMS + 1)    { loss_off = OUT_ELEMS; }

    cudaFuncSetAttribute(k_gemm_store,
                         cudaFuncAttributeMaxDynamicSharedMemorySize, 3 * 67584);

    k_transpose<<<dim3(32, 8, 16), dim3(32, 8)>>>(z);
    k_castcb<<<8192, 256>>>(cb);
    k_rownorm<<<MROWS, 256>>>();
    k_gemm_store<<<128, GTHREADS, 3 * 67584>>>();   // MMA + int8 P + rowmax
    k_filter<<<MROWS / 8, 256>>>();                 // candidates vs final thr
    k_rescore<<<MROWS, 256>>>(cb, dout, idx_off);
    k_loss<<<1, 256>>>(dout, loss_off);
    k_output<<<dim3(4, 256, 16), 256>>>(z, cb, dout);
}

// round 15
// speedup vs baseline: 227.8786x; 227.8786x over previous
#include <cuda_runtime.h>
#include <cuda_bf16.h>
#include <cstdint>

#define MROWS 16384
#define NCODES 16384
#define DDIM 256
#define OUT_ELEMS (16 * 256 * 32 * 32)   // 4194304

#define BM 128                 // rows per CTA
#define BN 128                 // codebook rows per chunk
#define NCHUNK (NCODES / BN)   // 128
#define CAP 128
#define MARGIN_P 4e-4f
#define QSCALE 51200.0f        // int8 quant scale; ulp = 1.953e-5
#define QSLACK 2.5e-5f         // > half-ulp + fp fuzz
#define GTHREADS 512

#define ASTRIDE 264            // bf16 elems per smem row (256 + 8 pad)
#define ROWB (ASTRIDE * 2)     // 528 bytes; 528 % 128 = 16 -> conflict-free ldmatrix

// ---- device scratch ----
__device__ float          g_Zt[MROWS * DDIM];     // fp32 transposed z
__device__ __nv_bfloat16  g_Ztb[MROWS * DDIM];    // bf16 transposed z
__device__ __nv_bfloat16  g_CBb[NCODES * DDIM];   // bf16 codebook
__device__ signed char    g_P8[(size_t)MROWS * NCODES];  // 256 MB quantized scores
__device__ float          g_rowmaxf[MROWS];       // final per-row max p (fp32)
__device__ float          g_A[MROWS];             // |z_row|^2
__device__ int            g_cnt[MROWS];           // candidate counts
__device__ int            g_list[MROWS * CAP];    // candidate codebook indices
__device__ int            g_idx[MROWS];           // final argmin index
__device__ float          g_partial[MROWS];       // per-row sum (e-z)^2

// ======================= portable PTX helpers (sm_80+) =======================
__device__ __forceinline__ uint32_t smem_u32(const void* p) {
    uint32_t a;
    asm("{ .reg .u64 t; cvta.to.shared.u64 t, %1; cvt.u32.u64 %0, t; }" : "=r"(a) : "l"(p));
    return a;
}
__device__ __forceinline__ void ldmat4(uint32_t* r, uint32_t addr) {
    asm volatile("ldmatrix.sync.aligned.m8n8.x4.shared.b16 {%0,%1,%2,%3}, [%4];"
                 : "=r"(r[0]), "=r"(r[1]), "=r"(r[2]), "=r"(r[3]) : "r"(addr));
}
__device__ __forceinline__ void mma16816(float* d, const uint32_t* a,
                                         uint32_t b0, uint32_t b1) {
    asm volatile(
        "mma.sync.aligned.m16n8k16.row.col.f32.bf16.bf16.f32 "
        "{%0,%1,%2,%3}, {%4,%5,%6,%7}, {%8,%9}, {%0,%1,%2,%3};"
        : "+f"(d[0]), "+f"(d[1]), "+f"(d[2]), "+f"(d[3])
        : "r"(a[0]), "r"(a[1]), "r"(a[2]), "r"(a[3]), "r"(b0), "r"(b1));
}
__device__ __forceinline__ void cp_async16(uint32_t dst, const void* src) {
    asm volatile("cp.async.cg.shared.global [%0], [%1], 16;" :: "r"(dst), "l"(src));
}
#define CP_COMMIT() asm volatile("cp.async.commit_group;" ::: "memory")
#define CP_WAIT0()  asm volatile("cp.async.wait_group 0;" ::: "memory")

__device__ __forceinline__ int q8(float p) {
    return __float2int_rn(fminf(fmaxf(p * QSCALE, -127.0f), 127.0f));
}

// ======================= transpose + bf16 cast of z =======================
__global__ void k_transpose(const float* __restrict__ z) {
    __shared__ float tile[32][33];
    const int b  = blockIdx.z;
    const int c0 = blockIdx.y * 32;
    const int h0 = blockIdx.x * 32;
    const int tx = threadIdx.x, ty = threadIdx.y;
#pragma unroll
    for (int i = 0; i < 32; i += 8)
        tile[ty + i][tx] = z[(b * 256 + c0 + ty + i) * 1024 + h0 + tx];
    __syncthreads();
#pragma unroll
    for (int i = 0; i < 32; i += 8) {
        const float v = tile[tx][ty + i];
        const int   o = (b * 1024 + h0 + ty + i) * 256 + c0 + tx;
        g_Zt[o]  = v;
        g_Ztb[o] = __float2bfloat16(v);
    }
}

// ======================= codebook -> bf16 =======================
__global__ void k_castcb(const float* __restrict__ cb) {
    const int i = blockIdx.x * 256 + threadIdx.x;     // over float2 elems
    float2 v = reinterpret_cast<const float2*>(cb)[i];
    reinterpret_cast<__nv_bfloat162*>(g_CBb)[i] = __float22bfloat162_rn(v);
}

// ======================= per-row |z|^2  (+ zero cand counts) ==============
__global__ void k_rownorm() {
    const int row = blockIdx.x;
    const int tid = threadIdx.x;
    float v = g_Zt[row * DDIM + tid];
    float s = v * v;
#pragma unroll
    for (int o = 16; o > 0; o >>= 1) s += __shfl_down_sync(0xffffffffu, s, o);
    __shared__ float red[8];
    if ((tid & 31) == 0) red[tid >> 5] = s;
    __syncthreads();
    if (tid == 0) {
        float t = red[0];
#pragma unroll
        for (int w = 1; w < 8; w++) t += red[w];
        g_A[row] = t;
        g_cnt[row] = 0;
    }
}

// ======================= single-pass bf16 mma.sync GEMM + int8 P store =====
// Grid: 128 CTAs x 512 threads (16 warps: 4 m-blocks x 4 n-blocks, 32x32 tile).
// Per chunk: MMA -> (SYNC: all warps done reading B) -> quantize scores to
// int8, stage into the consumed B smem buffer, dump 16 KB coalesced to g_P8,
// fold fp32 per-lane rowmax.
__global__ void __launch_bounds__(GTHREADS, 1) k_gemm_store() {
    extern __shared__ char dsm[];
    char* smA  = dsm;                       // 128*528 = 67584 B
    char* smB0 = dsm + 67584;
    char* smB1 = dsm + 2 * 67584;

    __shared__ float s_cmax[BM][4];

    const int tid = threadIdx.x;
    const int wid = tid >> 5;
    const int lid = tid & 31;
    const int m0  = blockIdx.x * BM;
    const int wm  = wid & 3;                // m-block (32 rows)
    const int wn  = wid >> 2;               // n-block (32 cols)

    // ---- stage A (rows m0..m0+127), padded rows ----
    for (int i = tid; i < 4096; i += GTHREADS) {
        const int r = i >> 5, c = i & 31;
        uint4 v = *reinterpret_cast<const uint4*>(
            g_Ztb + (size_t)(m0 + r) * DDIM + c * 8);
        *reinterpret_cast<uint4*>(smA + r * ROWB + c * 16) = v;
    }
    // ---- stage B chunk 0 via cp.async ----
    {
        const uint32_t b0 = smem_u32(smB0);
        for (int i = tid; i < 4096; i += GTHREADS) {
            const int r = i >> 5, c = i & 31;
            cp_async16(b0 + r * ROWB + c * 16, g_CBb + (size_t)r * DDIM + c * 8);
        }
        CP_COMMIT();
    }
    CP_WAIT0();
    __syncthreads();

    // ldmatrix lane bases. x4: lanes 0-15 rows (lid&15) @+0, 16-31 @+16B.
    const uint32_t aBase =
        smem_u32(smA) + (wm * 32 + (lid & 15)) * ROWB + (lid >> 4) * 16;
    const uint32_t bOff = (wn * 32 + (lid & 15)) * ROWB + (lid >> 4) * 16;
    const uint32_t bBase0 = smem_u32(smB0) + bOff;
    const uint32_t bBase1 = smem_u32(smB1) + bOff;

    // per-lane running maxes: [mi] x {low rows, high rows}
    float rmlow[2]  = {-3.4e38f, -3.4e38f};
    float rmhigh[2] = {-3.4e38f, -3.4e38f};

    const int rl0  = wm * 32 + (lid >> 2);      // mi=0 low row (local)
    const int colq = wn * 32 + 2 * (lid & 3);   // lane col base within chunk

    for (int c = 0; c < NCHUNK; c++) {
        const int buf = c & 1;
        // prefetch B(c+1) into the other buffer (overlaps MMA on chunk c)
        if (c + 1 < NCHUNK) {
            const uint32_t bd = smem_u32(buf ? smB0 : smB1);
            const size_t nbase = (size_t)(c + 1) * BN;
            for (int i = tid; i < 4096; i += GTHREADS) {
                const int r = i >> 5, cc = i & 31;
                cp_async16(bd + r * ROWB + cc * 16,
                           g_CBb + (nbase + r) * DDIM + cc * 8);
            }
        }
        CP_COMMIT();

        const uint32_t bB = buf ? bBase1 : bBase0;
        float acc[2][4][4];
#pragma unroll
        for (int mi = 0; mi < 2; mi++)
#pragma unroll
            for (int nj = 0; nj < 4; nj++)
#pragma unroll
                for (int t = 0; t < 4; t++) acc[mi][nj][t] = 0.0f;

        // frag double-buffer: [buf][0]=A rows 0-15, [1]=A rows 16-31,
        //                     [2]=B cols 0-15, [3]=B cols 16-31
        uint32_t fr[2][4][4];
        ldmat4(fr[0][0], aBase);
        ldmat4(fr[0][1], aBase + 16 * ROWB);
        ldmat4(fr[0][2], bB);
        ldmat4(fr[0][3], bB + 16 * ROWB);
#pragma unroll
        for (int kk = 0; kk < 16; kk++) {
            const int cu = kk & 1, nx = cu ^ 1;
            if (kk < 15) {
                ldmat4(fr[nx][0], aBase + (kk + 1) * 32);
                ldmat4(fr[nx][1], aBase + 16 * ROWB + (kk + 1) * 32);
                ldmat4(fr[nx][2], bB + (kk + 1) * 32);
                ldmat4(fr[nx][3], bB + 16 * ROWB + (kk + 1) * 32);
            }
            mma16816(acc[0][0], fr[cu][0], fr[cu][2][0], fr[cu][2][2]);
            mma16816(acc[0][1], fr[cu][0], fr[cu][2][1], fr[cu][2][3]);
            mma16816(acc[1][0], fr[cu][1], fr[cu][2][0], fr[cu][2][2]);
            mma16816(acc[1][1], fr[cu][1], fr[cu][2][1], fr[cu][2][3]);
            mma16816(acc[0][2], fr[cu][0], fr[cu][3][0], fr[cu][3][2]);
            mma16816(acc[0][3], fr[cu][0], fr[cu][3][1], fr[cu][3][3]);
            mma16816(acc[1][2], fr[cu][1], fr[cu][3][0], fr[cu][3][2]);
            mma16816(acc[1][3], fr[cu][1], fr[cu][3][1], fr[cu][3][3]);
        }

        // RACE FIX (R14 bug): all warps must finish reading B from this
        // buffer before ANY warp overwrites it with int8 staging bytes.
        __syncthreads();

        // ---- epilogue: quantize -> stage int8 in the consumed B buffer ----
        char* stage = buf ? smB1 : smB0;    // chunk c's B data is dead now
#pragma unroll
        for (int mi = 0; mi < 2; mi++) {
            const int rL = rl0 + mi * 16;
#pragma unroll
            for (int nj = 0; nj < 4; nj++) {
                const float a0 = acc[mi][nj][0], a1 = acc[mi][nj][1];
                const float a2 = acc[mi][nj][2], a3 = acc[mi][nj][3];
                rmlow[mi]  = fmaxf(rmlow[mi],  fmaxf(a0, a1));
                rmhigh[mi] = fmaxf(rmhigh[mi], fmaxf(a2, a3));
                const int off = colq + nj * 8;
                *reinterpret_cast<uint16_t*>(stage + rL * 128 + off) =
                    (uint16_t)((q8(a0) & 0xFF) | ((q8(a1) & 0xFF) << 8));
                *reinterpret_cast<uint16_t*>(stage + (rL + 8) * 128 + off) =
                    (uint16_t)((q8(a2) & 0xFF) | ((q8(a3) & 0xFF) << 8));
            }
        }
        __syncthreads();
        // ---- dump staging -> g_P8 (coalesced 16B stores) ----
        for (int i = tid; i < 1024; i += GTHREADS) {
            uint4 v = *reinterpret_cast<const uint4*>(stage + i * 16);
            const size_t gaddr =
                (size_t)(m0 + (i >> 3)) * NCODES + (size_t)c * BN + (i & 7) * 16;
            *reinterpret_cast<uint4*>(g_P8 + gaddr) = v;
        }
        CP_WAIT0();
        __syncthreads();
    }

    // ---- final rowmax reduce -> g_rowmaxf ----
#pragma unroll
    for (int mi = 0; mi < 2; mi++) {
        float ml = rmlow[mi], mh = rmhigh[mi];
        ml = fmaxf(ml, __shfl_xor_sync(0xffffffffu, ml, 1));
        ml = fmaxf(ml, __shfl_xor_sync(0xffffffffu, ml, 2));
        mh = fmaxf(mh, __shfl_xor_sync(0xffffffffu, mh, 1));
        mh = fmaxf(mh, __shfl_xor_sync(0xffffffffu, mh, 2));
        if ((lid & 3) == 0) {
            const int rl = wm * 32 + mi * 16 + (lid >> 2);
            s_cmax[rl][wn]     = ml;
            s_cmax[rl + 8][wn] = mh;
        }
    }
    __syncthreads();
    if (tid < BM)
        g_rowmaxf[m0 + tid] = fmaxf(fmaxf(s_cmax[tid][0], s_cmax[tid][1]),
                                    fmaxf(s_cmax[tid][2], s_cmax[tid][3]));
}

// ======================= candidate filter over int8 P =======================
// One warp per row (8 warps/block). SIMD byte-compare vs quantized threshold.
// qthr clamped to <=127 so saturated scores (incl. a clamped winner) always pass.
__global__ void __launch_bounds__(256) k_filter() {
    const int wid = threadIdx.x >> 5;
    const int lid = threadIdx.x & 31;
    const int row = blockIdx.x * 8 + wid;
    const float thr = g_rowmaxf[row] - (MARGIN_P + QSLACK);
    int qthr = (int)ceilf(thr * QSCALE);
    if (qthr > 127)  qthr = 127;
    if (qthr < -128) qthr = -128;
    const uint32_t qpat = (uint32_t)(qthr & 0xFF) * 0x01010101u;

    const uint4* prow =
        reinterpret_cast<const uint4*>(g_P8 + (size_t)row * NCODES);
    for (int i = lid; i < 1024; i += 32) {       // 1024 x 16B per row
        const uint4 v = __ldg(prow + i);
        uint32_t w[4] = {v.x, v.y, v.z, v.w};
#pragma unroll
        for (int j = 0; j < 4; j++) {
            uint32_t m = __vcmpges4(w[j], qpat);
            while (m) {                           // rare: ~13 hits / 16384
                const int b = (__ffs(m) - 1) >> 3;
                const int code = i * 16 + j * 4 + b;
                int s = atomicAdd(&g_cnt[row], 1);
                if (s < CAP) g_list[row * CAP + s] = code;
                m &= ~(0xFFu << (b * 8));
            }
        }
    }
}

// ======================= exact rescore + loss partial + idx ================
// One block (256 thr) per row. Rescore replicates R1 bit-exact arithmetic:
// acc = fmaf ascending k;  d = __fadd_rn(A, -2.0f*acc);  min d, tie -> min idx.
__global__ void k_rescore(const float* __restrict__ cb, float* __restrict__ dout,
                          int idx_off) {
    const int row = blockIdx.x;
    const int tid = threadIdx.x;
    __shared__ float zrow[DDIM];
    __shared__ float sd[256];
    __shared__ int   si[256];
    __shared__ int   s_bi;
    __shared__ float red[8];

    zrow[tid] = g_Zt[(size_t)row * DDIM + tid];
    const int cnt = g_cnt[row];
    const float Arow = g_A[row];
    __syncthreads();

    if (cnt <= CAP) {
        float d = __int_as_float(0x7f800000);
        int   bi = 0x7fffffff;
        if (tid < cnt) {
            bi = g_list[row * CAP + tid];
            const float* e = cb + (size_t)bi * DDIM;
            float acc = 0.0f;
#pragma unroll 8
            for (int k = 0; k < DDIM; k++) acc = fmaf(zrow[k], __ldg(e + k), acc);
            d = __fadd_rn(Arow, -2.0f * acc);
        }
        sd[tid] = d; si[tid] = bi;
        __syncthreads();
        for (int o = 128; o > 0; o >>= 1) {
            if (tid < o) {
                float od = sd[tid + o]; int oi = si[tid + o];
                if (od < sd[tid] || (od == sd[tid] && oi < si[tid])) {
                    sd[tid] = od; si[tid] = oi;
                }
            }
            __syncthreads();
        }
        if (tid == 0) s_bi = si[0];
    } else {
        // fallback: exact full scan (expected ~never with full-max threshold)
        float bd = __int_as_float(0x7f800000);
        int   bi = 0x7fffffff;
        for (int n = tid; n < NCODES; n += 256) {
            float acc = 0.0f;
            const float* e = cb + (size_t)n * DDIM;
#pragma unroll 8
            for (int k = 0; k < DDIM; k++) acc = fmaf(zrow[k], e[k], acc);
            float d = __fadd_rn(Arow, -2.0f * acc);
            if (d < bd || (d == bd && n < bi)) { bd = d; bi = n; }
        }
        sd[tid] = bd; si[tid] = bi;
        __syncthreads();
        for (int o = 128; o > 0; o >>= 1) {
            if (tid < o) {
                float od = sd[tid + o]; int oi = si[tid + o];
                if (od < sd[tid] || (od == sd[tid] && oi < si[tid])) {
                    sd[tid] = od; si[tid] = oi;
                }
            }
            __syncthreads();
        }
        if (tid == 0) s_bi = si[0];
    }
    __syncthreads();
    const int bi = s_bi;

    // ---- fused loss partial (bit-exact replica of old k_partial) ----
    const float e  = cb[(size_t)bi * DDIM + tid];
    const float zt = zrow[tid];
    const float t  = __fsub_rn(e, zt);
    float d2 = t * t;
#pragma unroll
    for (int o = 16; o > 0; o >>= 1) d2 += __shfl_down_sync(0xffffffffu, d2, o);
    if ((tid & 31) == 0) red[tid >> 5] = d2;
    __syncthreads();
    if (tid == 0) {
        float tot = red[0];
#pragma unroll
        for (int w = 1; w < 8; w++) tot += red[w];
        g_partial[row] = tot;
        g_idx[row] = bi;
        if (idx_off >= 0) dout[idx_off + row] = (float)bi;
    }
}

// ======================= final loss =======================
__global__ void k_loss(float* __restrict__ dout, int loss_off) {
    const int tid = threadIdx.x;
    float s = 0.0f;
    for (int i = tid; i < MROWS; i += 256) s += g_partial[i];
    __shared__ float red[256];
    red[tid] = s;
    __syncthreads();
    for (int o = 128; o > 0; o >>= 1) {
        if (tid < o) red[tid] += red[tid + o];
        __syncthreads();
    }
    if (tid == 0 && loss_off >= 0)
        dout[loss_off] = 1.25f * red[0] / (float)OUT_ELEMS;
}

// ======================= straight-through output =======================
__global__ void k_output(const float* __restrict__ z, const float* __restrict__ cb,
                         float* __restrict__ dout) {
    const int hw = blockIdx.x * 256 + threadIdx.x;
    const int c  = blockIdx.y;
    const int b  = blockIdx.z;
    const int row = (b << 10) + hw;
    const int n   = g_idx[row];
    const int off = (b * 256 + c) * 1024 + hw;
    const float zv = z[off];
    const float e  = cb[(size_t)n * DDIM + c];
    dout[off] = __fadd_rn(zv, __fsub_rn(e, zv));
}

extern "C" void kernel_launch(void* const* d_in, const int* in_sizes, int n_in,
                              void* d_out, int out_size) {
    const float* z  = (const float*)d_in[0];
    const float* cb = (const float*)d_in[1];
    float* dout = (float*)d_out;

    int loss_off = -1, idx_off = -1;
    if (out_size >= OUT_ELEMS + 1 + MROWS) { loss_off = OUT_ELEMS; idx_off = OUT_ELEMS + 1; }
    else if (out_size >= OUT_ELEMS + 1)    { loss_off = OUT_ELEMS; }

    cudaFuncSetAttribute(k_gemm_store,
                         cudaFuncAttributeMaxDynamicSharedMemorySize, 3 * 67584);

    k_transpose<<<dim3(32, 8, 16), dim3(32, 8)>>>(z);
    k_castcb<<<8192, 256>>>(cb);
    k_rownorm<<<MROWS, 256>>>();
    k_gemm_store<<<128, GTHREADS, 3 * 67584>>>();   // MMA + int8 P + rowmax
    k_filter<<<MROWS / 8, 256>>>();                 // candidates vs final thr
    k_rescore<<<MROWS, 256>>>(cb, dout, idx_off);
    k_loss<<<1, 256>>>(dout, loss_off);
    k_output<<<dim3(4, 256, 16), 256>>>(z, cb, dout);
}

// round 16
// speedup vs baseline: 241.1938x; 1.0584x over previous
#include <cuda_runtime.h>
#include <cuda_bf16.h>
#include <cstdint>

#define MROWS 16384
#define NCODES 16384
#define DDIM 256
#define OUT_ELEMS (16 * 256 * 32 * 32)   // 4194304

#define BM 128                 // rows per CTA
#define BN 128                 // codebook rows per chunk
#define NCHUNK (NCODES / BN)   // 128
#define CAP 128
#define MARGIN_P 4e-4f
#define QSCALE 51200.0f        // int8 quant scale; ulp = 1.953e-5
#define QSLACK 2.5e-5f         // > half-ulp + fp fuzz
#define GTHREADS 512

#define ASTRIDE 264            // bf16 elems per smem row (256 + 8 pad)
#define ROWB (ASTRIDE * 2)     // 528 bytes; 528 % 128 = 16 -> conflict-free ldmatrix

// ---- device scratch ----
__device__ float          g_Zt[MROWS * DDIM];     // fp32 transposed z
__device__ __nv_bfloat16  g_Ztb[MROWS * DDIM];    // bf16 transposed z
__device__ __nv_bfloat16  g_CBb[NCODES * DDIM];   // bf16 codebook
__device__ signed char    g_P8[(size_t)MROWS * NCODES];  // 256 MB quantized scores
__device__ float          g_rowmaxf[MROWS];       // final per-row max p (fp32)
__device__ float          g_A[MROWS];             // |z_row|^2
__device__ int            g_idx[MROWS];           // final argmin index
__device__ float          g_partial[MROWS];       // per-row sum (e-z)^2

// ======================= portable PTX helpers (sm_80+) =======================
__device__ __forceinline__ uint32_t smem_u32(const void* p) {
    uint32_t a;
    asm("{ .reg .u64 t; cvta.to.shared.u64 t, %1; cvt.u32.u64 %0, t; }" : "=r"(a) : "l"(p));
    return a;
}
__device__ __forceinline__ void ldmat4(uint32_t* r, uint32_t addr) {
    asm volatile("ldmatrix.sync.aligned.m8n8.x4.shared.b16 {%0,%1,%2,%3}, [%4];"
                 : "=r"(r[0]), "=r"(r[1]), "=r"(r[2]), "=r"(r[3]) : "r"(addr));
}
__device__ __forceinline__ void mma16816(float* d, const uint32_t* a,
                                         uint32_t b0, uint32_t b1) {
    asm volatile(
        "mma.sync.aligned.m16n8k16.row.col.f32.bf16.bf16.f32 "
        "{%0,%1,%2,%3}, {%4,%5,%6,%7}, {%8,%9}, {%0,%1,%2,%3};"
        : "+f"(d[0]), "+f"(d[1]), "+f"(d[2]), "+f"(d[3])
        : "r"(a[0]), "r"(a[1]), "r"(a[2]), "r"(a[3]), "r"(b0), "r"(b1));
}
__device__ __forceinline__ void cp_async16(uint32_t dst, const void* src) {
    asm volatile("cp.async.cg.shared.global [%0], [%1], 16;" :: "r"(dst), "l"(src));
}
#define CP_COMMIT() asm volatile("cp.async.commit_group;" ::: "memory")
#define CP_WAIT0()  asm volatile("cp.async.wait_group 0;" ::: "memory")

__device__ __forceinline__ int q8(float p) {
    return __float2int_rn(fminf(fmaxf(p * QSCALE, -127.0f), 127.0f));
}

// ======================= transpose + bf16 cast of z =======================
__global__ void k_transpose(const float* __restrict__ z) {
    __shared__ float tile[32][33];
    const int b  = blockIdx.z;
    const int c0 = blockIdx.y * 32;
    const int h0 = blockIdx.x * 32;
    const int tx = threadIdx.x, ty = threadIdx.y;
#pragma unroll
    for (int i = 0; i < 32; i += 8)
        tile[ty + i][tx] = z[(b * 256 + c0 + ty + i) * 1024 + h0 + tx];
    __syncthreads();
#pragma unroll
    for (int i = 0; i < 32; i += 8) {
        const float v = tile[tx][ty + i];
        const int   o = (b * 1024 + h0 + ty + i) * 256 + c0 + tx;
        g_Zt[o]  = v;
        g_Ztb[o] = __float2bfloat16(v);
    }
}

// ======================= codebook -> bf16 =======================
__global__ void k_castcb(const float* __restrict__ cb) {
    const int i = blockIdx.x * 256 + threadIdx.x;     // over float2 elems
    float2 v = reinterpret_cast<const float2*>(cb)[i];
    reinterpret_cast<__nv_bfloat162*>(g_CBb)[i] = __float22bfloat162_rn(v);
}

// ======================= per-row |z|^2 ==============
__global__ void k_rownorm() {
    const int row = blockIdx.x;
    const int tid = threadIdx.x;
    float v = g_Zt[row * DDIM + tid];
    float s = v * v;
#pragma unroll
    for (int o = 16; o > 0; o >>= 1) s += __shfl_down_sync(0xffffffffu, s, o);
    __shared__ float red[8];
    if ((tid & 31) == 0) red[tid >> 5] = s;
    __syncthreads();
    if (tid == 0) {
        float t = red[0];
#pragma unroll
        for (int w = 1; w < 8; w++) t += red[w];
        g_A[row] = t;
    }
}

// ======================= single-pass bf16 mma.sync GEMM + int8 P store =====
// (unchanged from R15 — protected win)
__global__ void __launch_bounds__(GTHREADS, 1) k_gemm_store() {
    extern __shared__ char dsm[];
    char* smA  = dsm;                       // 128*528 = 67584 B
    char* smB0 = dsm + 67584;
    char* smB1 = dsm + 2 * 67584;

    __shared__ float s_cmax[BM][4];

    const int tid = threadIdx.x;
    const int wid = tid >> 5;
    const int lid = tid & 31;
    const int m0  = blockIdx.x * BM;
    const int wm  = wid & 3;                // m-block (32 rows)
    const int wn  = wid >> 2;               // n-block (32 cols)

    // ---- stage A (rows m0..m0+127), padded rows ----
    for (int i = tid; i < 4096; i += GTHREADS) {
        const int r = i >> 5, c = i & 31;
        uint4 v = *reinterpret_cast<const uint4*>(
            g_Ztb + (size_t)(m0 + r) * DDIM + c * 8);
        *reinterpret_cast<uint4*>(smA + r * ROWB + c * 16) = v;
    }
    // ---- stage B chunk 0 via cp.async ----
    {
        const uint32_t b0 = smem_u32(smB0);
        for (int i = tid; i < 4096; i += GTHREADS) {
            const int r = i >> 5, c = i & 31;
            cp_async16(b0 + r * ROWB + c * 16, g_CBb + (size_t)r * DDIM + c * 8);
        }
        CP_COMMIT();
    }
    CP_WAIT0();
    __syncthreads();

    // ldmatrix lane bases. x4: lanes 0-15 rows (lid&15) @+0, 16-31 @+16B.
    const uint32_t aBase =
        smem_u32(smA) + (wm * 32 + (lid & 15)) * ROWB + (lid >> 4) * 16;
    const uint32_t bOff = (wn * 32 + (lid & 15)) * ROWB + (lid >> 4) * 16;
    const uint32_t bBase0 = smem_u32(smB0) + bOff;
    const uint32_t bBase1 = smem_u32(smB1) + bOff;

    // per-lane running maxes: [mi] x {low rows, high rows}
    float rmlow[2]  = {-3.4e38f, -3.4e38f};
    float rmhigh[2] = {-3.4e38f, -3.4e38f};

    const int rl0  = wm * 32 + (lid >> 2);      // mi=0 low row (local)
    const int colq = wn * 32 + 2 * (lid & 3);   // lane col base within chunk

    for (int c = 0; c < NCHUNK; c++) {
        const int buf = c & 1;
        // prefetch B(c+1) into the other buffer (overlaps MMA on chunk c)
        if (c + 1 < NCHUNK) {
            const uint32_t bd = smem_u32(buf ? smB0 : smB1);
            const size_t nbase = (size_t)(c + 1) * BN;
            for (int i = tid; i < 4096; i += GTHREADS) {
                const int r = i >> 5, cc = i & 31;
                cp_async16(bd + r * ROWB + cc * 16,
                           g_CBb + (nbase + r) * DDIM + cc * 8);
            }
        }
        CP_COMMIT();

        const uint32_t bB = buf ? bBase1 : bBase0;
        float acc[2][4][4];
#pragma unroll
        for (int mi = 0; mi < 2; mi++)
#pragma unroll
            for (int nj = 0; nj < 4; nj++)
#pragma unroll
                for (int t = 0; t < 4; t++) acc[mi][nj][t] = 0.0f;

        // frag double-buffer
        uint32_t fr[2][4][4];
        ldmat4(fr[0][0], aBase);
        ldmat4(fr[0][1], aBase + 16 * ROWB);
        ldmat4(fr[0][2], bB);
        ldmat4(fr[0][3], bB + 16 * ROWB);
#pragma unroll
        for (int kk = 0; kk < 16; kk++) {
            const int cu = kk & 1, nx = cu ^ 1;
            if (kk < 15) {
                ldmat4(fr[nx][0], aBase + (kk + 1) * 32);
                ldmat4(fr[nx][1], aBase + 16 * ROWB + (kk + 1) * 32);
                ldmat4(fr[nx][2], bB + (kk + 1) * 32);
                ldmat4(fr[nx][3], bB + 16 * ROWB + (kk + 1) * 32);
            }
            mma16816(acc[0][0], fr[cu][0], fr[cu][2][0], fr[cu][2][2]);
            mma16816(acc[0][1], fr[cu][0], fr[cu][2][1], fr[cu][2][3]);
            mma16816(acc[1][0], fr[cu][1], fr[cu][2][0], fr[cu][2][2]);
            mma16816(acc[1][1], fr[cu][1], fr[cu][2][1], fr[cu][2][3]);
            mma16816(acc[0][2], fr[cu][0], fr[cu][3][0], fr[cu][3][2]);
            mma16816(acc[0][3], fr[cu][0], fr[cu][3][1], fr[cu][3][3]);
            mma16816(acc[1][2], fr[cu][1], fr[cu][3][0], fr[cu][3][2]);
            mma16816(acc[1][3], fr[cu][1], fr[cu][3][1], fr[cu][3][3]);
        }

        // RACE FIX: all warps must finish reading B before staging overwrites.
        __syncthreads();

        // ---- epilogue: quantize -> stage int8 in the consumed B buffer ----
        char* stage = buf ? smB1 : smB0;    // chunk c's B data is dead now
#pragma unroll
        for (int mi = 0; mi < 2; mi++) {
            const int rL = rl0 + mi * 16;
#pragma unroll
            for (int nj = 0; nj < 4; nj++) {
                const float a0 = acc[mi][nj][0], a1 = acc[mi][nj][1];
                const float a2 = acc[mi][nj][2], a3 = acc[mi][nj][3];
                rmlow[mi]  = fmaxf(rmlow[mi],  fmaxf(a0, a1));
                rmhigh[mi] = fmaxf(rmhigh[mi], fmaxf(a2, a3));
                const int off = colq + nj * 8;
                *reinterpret_cast<uint16_t*>(stage + rL * 128 + off) =
                    (uint16_t)((q8(a0) & 0xFF) | ((q8(a1) & 0xFF) << 8));
                *reinterpret_cast<uint16_t*>(stage + (rL + 8) * 128 + off) =
                    (uint16_t)((q8(a2) & 0xFF) | ((q8(a3) & 0xFF) << 8));
            }
        }
        __syncthreads();
        // ---- dump staging -> g_P8 (coalesced 16B stores) ----
        for (int i = tid; i < 1024; i += GTHREADS) {
            uint4 v = *reinterpret_cast<const uint4*>(stage + i * 16);
            const size_t gaddr =
                (size_t)(m0 + (i >> 3)) * NCODES + (size_t)c * BN + (i & 7) * 16;
            *reinterpret_cast<uint4*>(g_P8 + gaddr) = v;
        }
        CP_WAIT0();
        __syncthreads();
    }

    // ---- final rowmax reduce -> g_rowmaxf ----
#pragma unroll
    for (int mi = 0; mi < 2; mi++) {
        float ml = rmlow[mi], mh = rmhigh[mi];
        ml = fmaxf(ml, __shfl_xor_sync(0xffffffffu, ml, 1));
        ml = fmaxf(ml, __shfl_xor_sync(0xffffffffu, ml, 2));
        mh = fmaxf(mh, __shfl_xor_sync(0xffffffffu, mh, 1));
        mh = fmaxf(mh, __shfl_xor_sync(0xffffffffu, mh, 2));
        if ((lid & 3) == 0) {
            const int rl = wm * 32 + mi * 16 + (lid >> 2);
            s_cmax[rl][wn]     = ml;
            s_cmax[rl + 8][wn] = mh;
        }
    }
    __syncthreads();
    if (tid < BM)
        g_rowmaxf[m0 + tid] = fmaxf(fmaxf(s_cmax[tid][0], s_cmax[tid][1]),
                                    fmaxf(s_cmax[tid][2], s_cmax[tid][3]));
}

// ========== fused select: filter (int8 SIMD) + exact rescore + partial =====
// One block (256 thr) per row. Candidate list lives in smem (no global
// g_cnt/g_list round-trip, no separate filter launch). Rescore replicates R1
// bit-exact arithmetic; per-row loss partial fused (bit-exact).
__global__ void __launch_bounds__(256) k_select(const float* __restrict__ cb,
                                                float* __restrict__ dout,
                                                int idx_off) {
    const int row = blockIdx.x;
    const int tid = threadIdx.x;
    __shared__ float zrow[DDIM];
    __shared__ int   scnt;
    __shared__ int   slist[CAP];
    __shared__ float sd[256];
    __shared__ int   si[256];
    __shared__ int   s_bi;
    __shared__ float red[8];

    zrow[tid] = g_Zt[(size_t)row * DDIM + tid];
    if (tid == 0) scnt = 0;
    const float Arow = g_A[row];
    const float thr = g_rowmaxf[row] - (MARGIN_P + QSLACK);
    int qthr = (int)ceilf(thr * QSCALE);
    if (qthr > 127)  qthr = 127;
    if (qthr < -128) qthr = -128;
    const uint32_t qpat = (uint32_t)(qthr & 0xFF) * 0x01010101u;
    __syncthreads();

    // ---- filter: 16 KB row of int8 scores, SIMD byte compare ----
    const uint4* prow =
        reinterpret_cast<const uint4*>(g_P8 + (size_t)row * NCODES);
#pragma unroll
    for (int it = 0; it < 4; it++) {
        const int i = it * 256 + tid;
        const uint4 v = __ldg(prow + i);
        uint32_t w[4] = {v.x, v.y, v.z, v.w};
#pragma unroll
        for (int j = 0; j < 4; j++) {
            uint32_t m = __vcmpges4(w[j], qpat);
            while (m) {                           // rare: ~13 hits / 16384
                const int b = (__ffs(m) - 1) >> 3;
                const int code = i * 16 + j * 4 + b;
                int s = atomicAdd(&scnt, 1);
                if (s < CAP) slist[s] = code;
                m &= ~(0xFFu << (b * 8));
            }
        }
    }
    __syncthreads();
    const int cnt = scnt;

    if (cnt <= CAP) {
        float d = __int_as_float(0x7f800000);
        int   bi = 0x7fffffff;
        if (tid < cnt) {
            bi = slist[tid];
            const float* e = cb + (size_t)bi * DDIM;
            float acc = 0.0f;
#pragma unroll 8
            for (int k = 0; k < DDIM; k++) acc = fmaf(zrow[k], __ldg(e + k), acc);
            d = __fadd_rn(Arow, -2.0f * acc);
        }
        sd[tid] = d; si[tid] = bi;
        __syncthreads();
        for (int o = 128; o > 0; o >>= 1) {
            if (tid < o) {
                float od = sd[tid + o]; int oi = si[tid + o];
                if (od < sd[tid] || (od == sd[tid] && oi < si[tid])) {
                    sd[tid] = od; si[tid] = oi;
                }
            }
            __syncthreads();
        }
        if (tid == 0) s_bi = si[0];
    } else {
        // fallback: exact full scan (expected ~never with full-max threshold)
        float bd = __int_as_float(0x7f800000);
        int   bi = 0x7fffffff;
        for (int n = tid; n < NCODES; n += 256) {
            float acc = 0.0f;
            const float* e = cb + (size_t)n * DDIM;
#pragma unroll 8
            for (int k = 0; k < DDIM; k++) acc = fmaf(zrow[k], e[k], acc);
            float d = __fadd_rn(Arow, -2.0f * acc);
            if (d < bd || (d == bd && n < bi)) { bd = d; bi = n; }
        }
        sd[tid] = bd; si[tid] = bi;
        __syncthreads();
        for (int o = 128; o > 0; o >>= 1) {
            if (tid < o) {
                float od = sd[tid + o]; int oi = si[tid + o];
                if (od < sd[tid] || (od == sd[tid] && oi < si[tid])) {
                    sd[tid] = od; si[tid] = oi;
                }
            }
            __syncthreads();
        }
        if (tid == 0) s_bi = si[0];
    }
    __syncthreads();
    const int bi = s_bi;

    // ---- fused loss partial (bit-exact) ----
    const float e  = cb[(size_t)bi * DDIM + tid];
    const float zt = zrow[tid];
    const float t  = __fsub_rn(e, zt);
    float d2 = t * t;
#pragma unroll
    for (int o = 16; o > 0; o >>= 1) d2 += __shfl_down_sync(0xffffffffu, d2, o);
    if ((tid & 31) == 0) red[tid >> 5] = d2;
    __syncthreads();
    if (tid == 0) {
        float tot = red[0];
#pragma unroll
        for (int w = 1; w < 8; w++) tot += red[w];
        g_partial[row] = tot;
        g_idx[row] = bi;
        if (idx_off >= 0) dout[idx_off + row] = (float)bi;
    }
}

// ======================= final loss =======================
__global__ void k_loss(float* __restrict__ dout, int loss_off) {
    const int tid = threadIdx.x;
    float s = 0.0f;
    for (int i = tid; i < MROWS; i += 256) s += g_partial[i];
    __shared__ float red[256];
    red[tid] = s;
    __syncthreads();
    for (int o = 128; o > 0; o >>= 1) {
        if (tid < o) red[tid] += red[tid + o];
        __syncthreads();
    }
    if (tid == 0 && loss_off >= 0)
        dout[loss_off] = 1.25f * red[0] / (float)OUT_ELEMS;
}

// ======================= straight-through output (tiled gather) ============
// Block = 32 hw x 256 c. Gathered codebook rows staged in padded smem
// (stride 257 -> conflict-free on scb[hw][c] reads). z reads and out writes
// fully coalesced. out = fp32(z + fp32(z_q - z)) bit-exact as before.
__global__ void __launch_bounds__(256) k_output(const float* __restrict__ z,
                                                const float* __restrict__ cb,
                                                float* __restrict__ dout) {
    __shared__ float scb[32][257];
    __shared__ int   sidx[32];
    const int b   = blockIdx.y;            // 0..15
    const int hw0 = blockIdx.x * 32;       // 0..31 tiles
    const int tid = threadIdx.x;

    if (tid < 32) sidx[tid] = g_idx[(b << 10) + hw0 + tid];
    __syncthreads();

    // load 32 gathered codebook rows (coalesced float4 per row-slice)
#pragma unroll
    for (int rr = 0; rr < 4; rr++) {
        const int r = rr * 8 + (tid >> 5);
        const int c = (tid & 31) * 8;
        const float4* src =
            reinterpret_cast<const float4*>(cb + (size_t)sidx[r] * DDIM + c);
        const float4 v0 = src[0], v1 = src[1];
        scb[r][c + 0] = v0.x; scb[r][c + 1] = v0.y;
        scb[r][c + 2] = v0.z; scb[r][c + 3] = v0.w;
        scb[r][c + 4] = v1.x; scb[r][c + 5] = v1.y;
        scb[r][c + 6] = v1.z; scb[r][c + 7] = v1.w;
    }
    __syncthreads();

    // write out: 256 threads = 8 c-rows x 32 hw lanes, 32 iterations
    const int hw = tid & 31;
#pragma unroll 4
    for (int i = 0; i < 32; i++) {
        const int c = i * 8 + (tid >> 5);
        const int off = (b * 256 + c) * 1024 + hw0 + hw;
        const float zv = z[off];
        const float e  = scb[hw][c];
        dout[off] = __fadd_rn(zv, __fsub_rn(e, zv));
    }
}

extern "C" void kernel_launch(void* const* d_in, const int* in_sizes, int n_in,
                              void* d_out, int out_size) {
    const float* z  = (const float*)d_in[0];
    const float* cb = (const float*)d_in[1];
    float* dout = (float*)d_out;

    int loss_off = -1, idx_off = -1;
    if (out_size >= OUT_ELEMS + 1 + MROWS) { loss_off = OUT_ELEMS; idx_off = OUT_ELEMS + 1; }
    else if (out_size >= OUT_ELEMS + 1)    { loss_off = OUT_ELEMS; }

    cudaFuncSetAttribute(k_gemm_store,
                         cudaFuncAttributeMaxDynamicSharedMemorySize, 3 * 67584);

    k_transpose<<<dim3(32, 8, 16), dim3(32, 8)>>>(z);
    k_castcb<<<8192, 256>>>(cb);
    k_rownorm<<<MROWS, 256>>>();
    k_gemm_store<<<128, GTHREADS, 3 * 67584>>>();   // MMA + int8 P + rowmax
    k_select<<<MROWS, 256>>>(cb, dout, idx_off);    // filter+rescore+partial
    k_loss<<<1, 256>>>(dout, loss_off);
    k_output<<<dim3(32, 16), 256>>>(z, cb, dout);
}